// round 4
// baseline (speedup 1.0000x reference)
#include <cuda_runtime.h>

#define HDIM 128

// ---------------- scratch (static __device__ arrays; no allocation) ----------
#define MAXM 50176
#define MAXL 401408
#define MHS  ((long long)MAXM * HDIM)

__device__ float g_arena[12ll * MHS];   // 12 [M,H] fp32 scratch matrices
__device__ int   g_counts[MAXM];
__device__ int   g_cursor[MAXM];
__device__ int   g_offsets[MAXM + 1];
__device__ int   g_chis[MAXL];
__device__ float g_eexp[MAXL];

// arena slots
// 0 WiX  1 WfX  2 WoX  3 WcX  4 Bx  5 Ah  6 Ufh  7 UiH  8 UcH  9 UoH  10 hhat  11 sfc

__device__ __forceinline__ float sigmf(float x) {
    return __fdividef(1.f, 1.f + __expf(-x));
}
__device__ __forceinline__ float tanhf_(float x) {
    float e = __expf(2.f * x);
    return 1.f - __fdividef(2.f, e + 1.f);
}

// ---------------- batched NT GEMM: C[m,n] = sum_k A[m,k]*B[n,k] (+bias[n]) ---
// K = N = 128 fixed. BM=128, BN=128, BK=16, 256 threads, 8x8 per thread.
struct GemmBatch {
    const float* A[8];
    const float* B[8];
    const float* bias[8];
    float*       C[8];
};

__global__ __launch_bounds__(256) void gemm_nt_kernel(GemmBatch p, int M)
{
    const int z = blockIdx.z;
    const float* __restrict__ A    = p.A[z];
    const float* __restrict__ B    = p.B[z];
    const float* __restrict__ bias = p.bias[z];
    float*       __restrict__ C    = p.C[z];

    __shared__ float As[16][132];
    __shared__ float Bs[16][132];

    const int tid  = threadIdx.x;
    const int row0 = blockIdx.x * 128;
    const int tm   = tid >> 4;   // 0..15
    const int tn   = tid & 15;   // 0..15

    float acc[8][8];
#pragma unroll
    for (int i = 0; i < 8; i++)
#pragma unroll
        for (int j = 0; j < 8; j++) acc[i][j] = 0.f;

    for (int kc = 0; kc < HDIM; kc += 16) {
#pragma unroll
        for (int i = 0; i < 2; i++) {
            int f  = tid * 2 + i;          // 0..511 float4 slots
            int r  = f >> 2;               // row within tile (0..127)
            int kq = (f & 3) * 4;          // k offset within chunk
            int row = row0 + r;
            float4 va = make_float4(0.f, 0.f, 0.f, 0.f);
            if (row < M) va = *(const float4*)(A + (long long)row * HDIM + kc + kq);
            As[kq + 0][r] = va.x; As[kq + 1][r] = va.y;
            As[kq + 2][r] = va.z; As[kq + 3][r] = va.w;
            float4 vb = *(const float4*)(B + r * HDIM + kc + kq);  // N=128 always full
            Bs[kq + 0][r] = vb.x; Bs[kq + 1][r] = vb.y;
            Bs[kq + 2][r] = vb.z; Bs[kq + 3][r] = vb.w;
        }
        __syncthreads();
#pragma unroll
        for (int k = 0; k < 16; k++) {
            float a[8], b[8];
            *(float4*)&a[0] = *(const float4*)&As[k][tm * 8];
            *(float4*)&a[4] = *(const float4*)&As[k][tm * 8 + 4];
            *(float4*)&b[0] = *(const float4*)&Bs[k][tn * 8];
            *(float4*)&b[4] = *(const float4*)&Bs[k][tn * 8 + 4];
#pragma unroll
            for (int i = 0; i < 8; i++)
#pragma unroll
                for (int j = 0; j < 8; j++)
                    acc[i][j] = fmaf(a[i], b[j], acc[i][j]);
        }
        __syncthreads();
    }

    float bb[8];
    if (bias) {
        *(float4*)&bb[0] = *(const float4*)(bias + tn * 8);
        *(float4*)&bb[4] = *(const float4*)(bias + tn * 8 + 4);
    } else {
#pragma unroll
        for (int j = 0; j < 8; j++) bb[j] = 0.f;
    }
#pragma unroll
    for (int i = 0; i < 8; i++) {
        int row = row0 + tm * 8 + i;
        if (row < M) {
            float4 c0, c1;
            c0.x = acc[i][0] + bb[0]; c0.y = acc[i][1] + bb[1];
            c0.z = acc[i][2] + bb[2]; c0.w = acc[i][3] + bb[3];
            c1.x = acc[i][4] + bb[4]; c1.y = acc[i][5] + bb[5];
            c1.z = acc[i][6] + bb[6]; c1.w = acc[i][7] + bb[7];
            *(float4*)(C + (long long)row * HDIM + tn * 8)     = c0;
            *(float4*)(C + (long long)row * HDIM + tn * 8 + 4) = c1;
        }
    }
}

// ---------------- CSR build -------------------------------------------------
__global__ void zero_int_kernel(int M)
{
    int i = blockIdx.x * blockDim.x + threadIdx.x;
    if (i < M) { g_counts[i] = 0; g_cursor[i] = 0; }
}

__global__ void hist_kernel(const int* __restrict__ ci, int L)
{
    int i = blockIdx.x * blockDim.x + threadIdx.x;
    if (i < L) atomicAdd(&g_counts[ci[i]], 1);
}

__global__ void scan_kernel(int M)
{
    __shared__ int warpsum[32];
    __shared__ int carry_s;
    const int tid  = threadIdx.x;
    const int lane = tid & 31, wid = tid >> 5;
    if (tid == 0) carry_s = 0;
    __syncthreads();
    for (int base = 0; base < M; base += 1024) {
        int i = base + tid;
        int v = (i < M) ? g_counts[i] : 0;
        int x = v;
#pragma unroll
        for (int off = 1; off < 32; off <<= 1) {
            int t = __shfl_up_sync(0xffffffffu, x, off);
            if (lane >= off) x += t;
        }
        if (lane == 31) warpsum[wid] = x;
        __syncthreads();
        if (wid == 0) {
            int y = warpsum[lane];
#pragma unroll
            for (int off = 1; off < 32; off <<= 1) {
                int t = __shfl_up_sync(0xffffffffu, y, off);
                if (lane >= off) y += t;
            }
            warpsum[lane] = y;
        }
        __syncthreads();
        int wpre  = (wid > 0) ? warpsum[wid - 1] : 0;
        int incl  = x + wpre;
        int carry = carry_s;
        if (i < M) g_offsets[i] = carry + incl - v;
        __syncthreads();
        if (tid == 1023) carry_s = carry + incl;
        __syncthreads();
    }
    if (threadIdx.x == 0) g_offsets[M] = carry_s;
}

__global__ void scatter_kernel(const int* __restrict__ ci, const int* __restrict__ chi, int L)
{
    int i = blockIdx.x * blockDim.x + threadIdx.x;
    if (i < L) {
        int c   = ci[i];
        int pos = g_offsets[c] + atomicAdd(&g_cursor[c], 1);
        g_chis[pos] = chi[i];
    }
}

// ---------------- per-segment attention + f-gate accumulation ---------------
// warp per segment m:
//   pass1: e_l = dot(tanh(Ah[chi]+Bx[m]), v_w); accumulate sum(exp(e))
//   pass2: attn = exp/sum; hhat += attn*child_h[chi];
//          sfc  += sigmoid(WfX[m]+Ufh[chi]) * child_c[chi]
__global__ __launch_bounds__(256) void segment_kernel(
    const float* __restrict__ Bx, const float* __restrict__ Ah,
    const float* __restrict__ WfX, const float* __restrict__ Ufh,
    const float* __restrict__ child_h, const float* __restrict__ child_c,
    const float* __restrict__ v_w,
    float* __restrict__ hhat, float* __restrict__ sfc, int M)
{
    int warp = (blockIdx.x * blockDim.x + threadIdx.x) >> 5;
    int lane = threadIdx.x & 31;
    if (warp >= M) return;
    const int m = warp;
    const long long mo = (long long)m * HDIM + lane * 4;

    float4 bx = *(const float4*)(Bx + mo);
    float4 vv = *(const float4*)(v_w + lane * 4);

    int s0 = g_offsets[m], s1 = g_offsets[m + 1];

    float ssum = 0.f;
    for (int e = s0; e < s1; e++) {
        int chi = g_chis[e];
        float4 ah = *(const float4*)(Ah + (long long)chi * HDIM + lane * 4);
        float p = tanhf_(ah.x + bx.x) * vv.x + tanhf_(ah.y + bx.y) * vv.y
                + tanhf_(ah.z + bx.z) * vv.z + tanhf_(ah.w + bx.w) * vv.w;
#pragma unroll
        for (int off = 16; off > 0; off >>= 1)
            p += __shfl_xor_sync(0xffffffffu, p, off);
        float ex = __expf(p);          // no max-subtraction: |e| <= ~11, safe in fp32
        ssum += ex;
        if (lane == 0) g_eexp[e] = ex;
    }

    float4 h4 = make_float4(0.f, 0.f, 0.f, 0.f);
    float4 f4 = make_float4(0.f, 0.f, 0.f, 0.f);
    if (s1 > s0) {
        float inv = __fdividef(1.f, ssum);
        float4 wfx = *(const float4*)(WfX + mo);
        for (int e = s0; e < s1; e++) {
            int chi = g_chis[e];
            float w = g_eexp[e] * inv;
            long long co = (long long)chi * HDIM + lane * 4;
            float4 ch = *(const float4*)(child_h + co);
            h4.x = fmaf(w, ch.x, h4.x); h4.y = fmaf(w, ch.y, h4.y);
            h4.z = fmaf(w, ch.z, h4.z); h4.w = fmaf(w, ch.w, h4.w);
            float4 uf = *(const float4*)(Ufh + co);
            float4 cc = *(const float4*)(child_c + co);
            f4.x = fmaf(sigmf(wfx.x + uf.x), cc.x, f4.x);
            f4.y = fmaf(sigmf(wfx.y + uf.y), cc.y, f4.y);
            f4.z = fmaf(sigmf(wfx.z + uf.z), cc.z, f4.z);
            f4.w = fmaf(sigmf(wfx.w + uf.w), cc.w, f4.w);
        }
    }
    *(float4*)(hhat + mo) = h4;
    *(float4*)(sfc  + mo) = f4;
}

// ---------------- fused gate epilogue ---------------------------------------
__global__ void finalize_kernel(
    const float* __restrict__ WiX, const float* __restrict__ UiH,
    const float* __restrict__ WcX, const float* __restrict__ UcH,
    const float* __restrict__ WoX, const float* __restrict__ UoH,
    const float* __restrict__ sfc,
    float* __restrict__ outh, float* __restrict__ outc, int n4)
{
    int i = blockIdx.x * blockDim.x + threadIdx.x;
    if (i >= n4) return;
    float4 wi = ((const float4*)WiX)[i], ui = ((const float4*)UiH)[i];
    float4 wc = ((const float4*)WcX)[i], uc = ((const float4*)UcH)[i];
    float4 wo = ((const float4*)WoX)[i], uo = ((const float4*)UoH)[i];
    float4 sf = ((const float4*)sfc)[i];
    float4 h4, c4;
#define DO_COMP(C)                                                   \
    {                                                                \
        float ig = sigmf(wi.C + ui.C);                               \
        float ct = tanhf_(wc.C + uc.C);                              \
        float c  = fmaf(ig, ct, sf.C);                               \
        float o  = sigmf(wo.C + uo.C);                               \
        c4.C = c;                                                    \
        h4.C = o * tanhf_(c);                                        \
    }
    DO_COMP(x) DO_COMP(y) DO_COMP(z) DO_COMP(w)
#undef DO_COMP
    ((float4*)outh)[i] = h4;
    ((float4*)outc)[i] = c4;
}

// ---------------- launch ----------------------------------------------------
extern "C" void kernel_launch(void* const* d_in, const int* in_sizes, int n_in,
                              void* d_out, int out_size)
{
    const float* x_emb   = (const float*)d_in[0];
    const float* child_h = (const float*)d_in[1];
    const float* child_c = (const float*)d_in[2];
    const int*   ci      = (const int*)d_in[3];
    const int*   chi     = (const int*)d_in[4];
    const float* Wi_w = (const float*)d_in[5];
    const float* Ui_w = (const float*)d_in[6];
    const float* Wf_w = (const float*)d_in[7];
    const float* Uf_w = (const float*)d_in[8];
    const float* Wo_w = (const float*)d_in[9];
    const float* Uo_w = (const float*)d_in[10];
    const float* Wc_w = (const float*)d_in[11];
    const float* Uc_w = (const float*)d_in[12];
    const float* Wa_w = (const float*)d_in[13];
    const float* Ua_w = (const float*)d_in[14];
    const float* Wi_b = (const float*)d_in[15];
    const float* Wf_b = (const float*)d_in[16];
    const float* Wo_b = (const float*)d_in[17];
    const float* Wc_b = (const float*)d_in[18];
    const float* Wa_b = (const float*)d_in[19];
    const float* v_w  = (const float*)d_in[20];

    const int M = in_sizes[0] / HDIM;
    const int L = in_sizes[3];

    float* arena = nullptr;
    cudaGetSymbolAddress((void**)&arena, g_arena);
    float* WiX  = arena + 0 * MHS;
    float* WfX  = arena + 1 * MHS;
    float* WoX  = arena + 2 * MHS;
    float* WcX  = arena + 3 * MHS;
    float* Bx   = arena + 4 * MHS;
    float* Ah   = arena + 5 * MHS;
    float* Ufh  = arena + 6 * MHS;
    float* UiH  = arena + 7 * MHS;
    float* UcH  = arena + 8 * MHS;
    float* UoH  = arena + 9 * MHS;
    float* hhat = arena + 10 * MHS;
    float* sfc  = arena + 11 * MHS;

    // CSR build (runs while GEMM batch 1 is queued behind on same stream)
    zero_int_kernel<<<(M + 255) / 256, 256>>>(M);
    hist_kernel<<<(L + 255) / 256, 256>>>(ci, L);
    scan_kernel<<<1, 1024>>>(M);
    scatter_kernel<<<(L + 255) / 256, 256>>>(ci, chi, L);

    // GEMM batch 1: x_emb x {Wi,Wf,Wo,Wc,Ua}, child_h x {Wa,Uf}
    GemmBatch b1 = {};
    b1.A[0] = x_emb;   b1.B[0] = Wi_w; b1.bias[0] = Wi_b; b1.C[0] = WiX;
    b1.A[1] = x_emb;   b1.B[1] = Wf_w; b1.bias[1] = Wf_b; b1.C[1] = WfX;
    b1.A[2] = x_emb;   b1.B[2] = Wo_w; b1.bias[2] = Wo_b; b1.C[2] = WoX;
    b1.A[3] = x_emb;   b1.B[3] = Wc_w; b1.bias[3] = Wc_b; b1.C[3] = WcX;
    b1.A[4] = x_emb;   b1.B[4] = Ua_w; b1.bias[4] = nullptr; b1.C[4] = Bx;
    b1.A[5] = child_h; b1.B[5] = Wa_w; b1.bias[5] = Wa_b; b1.C[5] = Ah;
    b1.A[6] = child_h; b1.B[6] = Uf_w; b1.bias[6] = nullptr; b1.C[6] = Ufh;
    dim3 g1((M + 127) / 128, 1, 7);
    gemm_nt_kernel<<<g1, 256>>>(b1, M);

    // attention + f-gate segment reduction
    segment_kernel<<<(M + 7) / 8, 256>>>(Bx, Ah, WfX, Ufh, child_h, child_c,
                                         v_w, hhat, sfc, M);

    // GEMM batch 2: hhat x {Ui,Uc,Uo}
    GemmBatch b2 = {};
    b2.A[0] = hhat; b2.B[0] = Ui_w; b2.bias[0] = nullptr; b2.C[0] = UiH;
    b2.A[1] = hhat; b2.B[1] = Uc_w; b2.bias[1] = nullptr; b2.C[1] = UcH;
    b2.A[2] = hhat; b2.B[2] = Uo_w; b2.bias[2] = nullptr; b2.C[2] = UoH;
    dim3 g2((M + 127) / 128, 1, 3);
    gemm_nt_kernel<<<g2, 256>>>(b2, M);

    float* outh = (float*)d_out;
    float* outc = outh + (long long)M * HDIM;
    finalize_kernel<<<(M * 32 + 255) / 256, 256>>>(WiX, UiH, WcX, UcH, WoX, UoH,
                                                   sfc, outh, outc, M * 32);
}

// round 5
// speedup vs baseline: 1.0669x; 1.0669x over previous
#include <cuda_runtime.h>

#define HDIM 128

// ---------------- scratch (static __device__ arrays; no allocation) ----------
#define MAXM 50176
#define MAXL 401408
#define MHS  ((long long)MAXM * HDIM)

__device__ float g_arena[12ll * MHS];   // 12 [M,H] fp32 scratch matrices
__device__ int   g_counts[MAXM];
__device__ int   g_cursor[MAXM];
__device__ int   g_offsets[MAXM + 1];
__device__ int   g_chis[MAXL];
__device__ float g_eexp[MAXL];

// arena slots
// 0 WiX  1 WfX  2 WoX  3 WcX  4 Bx  5 Ah  6 Ufh  7 UiH  8 UcH  9 UoH  10 hhat  11 sfc

__device__ __forceinline__ float sigmf(float x) {
    return __fdividef(1.f, 1.f + __expf(-x));
}
__device__ __forceinline__ float tanhf_(float x) {
    float e = __expf(2.f * x);
    return 1.f - __fdividef(2.f, e + 1.f);
}

// ---------------- batched NT GEMM: C[m,n] = sum_k A[m,k]*B[n,k] (+bias[n]) ---
// K = N = 128 fixed. BM=128, BN=128, BK=16, 256 threads, 8x8 per thread.
// Inner loop uses packed fma.rn.f32x2 (FFMA2): 2 FMAs per fma-pipe issue slot.
struct GemmBatch {
    const float* A[8];
    const float* B[8];
    const float* bias[8];
    float*       C[8];
};

__device__ __forceinline__ unsigned long long pack2(float lo, float hi) {
    unsigned long long v;
    asm("mov.b64 %0, {%1, %2};" : "=l"(v) : "r"(__float_as_uint(lo)), "r"(__float_as_uint(hi)));
    return v;
}
__device__ __forceinline__ void unpack2(unsigned long long v, float& lo, float& hi) {
    unsigned int l, h;
    asm("mov.b64 {%0, %1}, %2;" : "=r"(l), "=r"(h) : "l"(v));
    lo = __uint_as_float(l);
    hi = __uint_as_float(h);
}

__global__ __launch_bounds__(256) void gemm_nt_kernel(GemmBatch p, int M)
{
    const int z = blockIdx.z;
    const float* __restrict__ A    = p.A[z];
    const float* __restrict__ B    = p.B[z];
    const float* __restrict__ bias = p.bias[z];
    float*       __restrict__ C    = p.C[z];

    __shared__ float As[16][132];
    __shared__ float Bs[16][132];

    const int tid  = threadIdx.x;
    const int row0 = blockIdx.x * 128;
    const int tm   = tid >> 4;   // 0..15
    const int tn   = tid & 15;   // 0..15

    // acc2[i][p] holds output cols (tn*8 + 2p, tn*8 + 2p + 1) for row tm*8+i
    unsigned long long acc2[8][4];
#pragma unroll
    for (int i = 0; i < 8; i++)
#pragma unroll
        for (int j = 0; j < 4; j++) acc2[i][j] = 0ull;

    for (int kc = 0; kc < HDIM; kc += 16) {
#pragma unroll
        for (int i = 0; i < 2; i++) {
            int f  = tid * 2 + i;          // 0..511 float4 slots
            int r  = f >> 2;               // row within tile (0..127)
            int kq = (f & 3) * 4;          // k offset within chunk
            int row = row0 + r;
            float4 va = make_float4(0.f, 0.f, 0.f, 0.f);
            if (row < M) va = *(const float4*)(A + (long long)row * HDIM + kc + kq);
            As[kq + 0][r] = va.x; As[kq + 1][r] = va.y;
            As[kq + 2][r] = va.z; As[kq + 3][r] = va.w;
            float4 vb = *(const float4*)(B + r * HDIM + kc + kq);  // N=128 always full
            Bs[kq + 0][r] = vb.x; Bs[kq + 1][r] = vb.y;
            Bs[kq + 2][r] = vb.z; Bs[kq + 3][r] = vb.w;
        }
        __syncthreads();
#pragma unroll
        for (int k = 0; k < 16; k++) {
            float a[8], b[8];
            *(float4*)&a[0] = *(const float4*)&As[k][tm * 8];
            *(float4*)&a[4] = *(const float4*)&As[k][tm * 8 + 4];
            *(float4*)&b[0] = *(const float4*)&Bs[k][tn * 8];
            *(float4*)&b[4] = *(const float4*)&Bs[k][tn * 8 + 4];

            unsigned long long bp[4], ap[8];
#pragma unroll
            for (int q = 0; q < 4; q++) bp[q] = pack2(b[2 * q], b[2 * q + 1]);
#pragma unroll
            for (int i = 0; i < 8; i++) ap[i] = pack2(a[i], a[i]);

#pragma unroll
            for (int i = 0; i < 8; i++)
#pragma unroll
                for (int q = 0; q < 4; q++)
                    asm("fma.rn.f32x2 %0, %1, %2, %3;"
                        : "=l"(acc2[i][q])
                        : "l"(ap[i]), "l"(bp[q]), "l"(acc2[i][q]));
        }
        __syncthreads();
    }

    float bb[8];
    if (bias) {
        *(float4*)&bb[0] = *(const float4*)(bias + tn * 8);
        *(float4*)&bb[4] = *(const float4*)(bias + tn * 8 + 4);
    } else {
#pragma unroll
        for (int j = 0; j < 8; j++) bb[j] = 0.f;
    }
#pragma unroll
    for (int i = 0; i < 8; i++) {
        int row = row0 + tm * 8 + i;
        if (row < M) {
            float c[8];
#pragma unroll
            for (int q = 0; q < 4; q++) {
                float lo, hi;
                unpack2(acc2[i][q], lo, hi);
                c[2 * q]     = lo + bb[2 * q];
                c[2 * q + 1] = hi + bb[2 * q + 1];
            }
            *(float4*)(C + (long long)row * HDIM + tn * 8)     = *(float4*)&c[0];
            *(float4*)(C + (long long)row * HDIM + tn * 8 + 4) = *(float4*)&c[4];
        }
    }
}

// ---------------- CSR build -------------------------------------------------
__global__ void zero_int_kernel(int M)
{
    int i = blockIdx.x * blockDim.x + threadIdx.x;
    if (i < M) { g_counts[i] = 0; g_cursor[i] = 0; }
}

__global__ void hist_kernel(const int* __restrict__ ci, int L)
{
    int i = blockIdx.x * blockDim.x + threadIdx.x;
    if (i < L) atomicAdd(&g_counts[ci[i]], 1);
}

__global__ void scan_kernel(int M)
{
    __shared__ int warpsum[32];
    __shared__ int carry_s;
    const int tid  = threadIdx.x;
    const int lane = tid & 31, wid = tid >> 5;
    if (tid == 0) carry_s = 0;
    __syncthreads();
    for (int base = 0; base < M; base += 1024) {
        int i = base + tid;
        int v = (i < M) ? g_counts[i] : 0;
        int x = v;
#pragma unroll
        for (int off = 1; off < 32; off <<= 1) {
            int t = __shfl_up_sync(0xffffffffu, x, off);
            if (lane >= off) x += t;
        }
        if (lane == 31) warpsum[wid] = x;
        __syncthreads();
        if (wid == 0) {
            int y = warpsum[lane];
#pragma unroll
            for (int off = 1; off < 32; off <<= 1) {
                int t = __shfl_up_sync(0xffffffffu, y, off);
                if (lane >= off) y += t;
            }
            warpsum[lane] = y;
        }
        __syncthreads();
        int wpre  = (wid > 0) ? warpsum[wid - 1] : 0;
        int incl  = x + wpre;
        int carry = carry_s;
        if (i < M) g_offsets[i] = carry + incl - v;
        __syncthreads();
        if (tid == 1023) carry_s = carry + incl;
        __syncthreads();
    }
    if (threadIdx.x == 0) g_offsets[M] = carry_s;
}

__global__ void scatter_kernel(const int* __restrict__ ci, const int* __restrict__ chi, int L)
{
    int i = blockIdx.x * blockDim.x + threadIdx.x;
    if (i < L) {
        int c   = ci[i];
        int pos = g_offsets[c] + atomicAdd(&g_cursor[c], 1);
        g_chis[pos] = chi[i];
    }
}

// ---------------- per-segment attention + f-gate accumulation ---------------
// warp per segment m:
//   pass1: e_l = dot(tanh(Ah[chi]+Bx[m]), v_w); accumulate sum(exp(e))
//   pass2: attn = exp/sum; hhat += attn*child_h[chi];
//          sfc  += sigmoid(WfX[m]+Ufh[chi]) * child_c[chi]
__global__ __launch_bounds__(256) void segment_kernel(
    const float* __restrict__ Bx, const float* __restrict__ Ah,
    const float* __restrict__ WfX, const float* __restrict__ Ufh,
    const float* __restrict__ child_h, const float* __restrict__ child_c,
    const float* __restrict__ v_w,
    float* __restrict__ hhat, float* __restrict__ sfc, int M)
{
    int warp = (blockIdx.x * blockDim.x + threadIdx.x) >> 5;
    int lane = threadIdx.x & 31;
    if (warp >= M) return;
    const int m = warp;
    const long long mo = (long long)m * HDIM + lane * 4;

    float4 bx = *(const float4*)(Bx + mo);
    float4 vv = *(const float4*)(v_w + lane * 4);

    int s0 = g_offsets[m], s1 = g_offsets[m + 1];

    float ssum = 0.f;
    for (int e = s0; e < s1; e++) {
        int chi = g_chis[e];
        float4 ah = *(const float4*)(Ah + (long long)chi * HDIM + lane * 4);
        float p = tanhf_(ah.x + bx.x) * vv.x + tanhf_(ah.y + bx.y) * vv.y
                + tanhf_(ah.z + bx.z) * vv.z + tanhf_(ah.w + bx.w) * vv.w;
#pragma unroll
        for (int off = 16; off > 0; off >>= 1)
            p += __shfl_xor_sync(0xffffffffu, p, off);
        float ex = __expf(p);          // no max-subtraction: |e| <= ~11, safe in fp32
        ssum += ex;
        if (lane == 0) g_eexp[e] = ex;
    }

    float4 h4 = make_float4(0.f, 0.f, 0.f, 0.f);
    float4 f4 = make_float4(0.f, 0.f, 0.f, 0.f);
    if (s1 > s0) {
        float inv = __fdividef(1.f, ssum);
        float4 wfx = *(const float4*)(WfX + mo);
        for (int e = s0; e < s1; e++) {
            int chi = g_chis[e];
            float w = g_eexp[e] * inv;
            long long co = (long long)chi * HDIM + lane * 4;
            float4 ch = *(const float4*)(child_h + co);
            h4.x = fmaf(w, ch.x, h4.x); h4.y = fmaf(w, ch.y, h4.y);
            h4.z = fmaf(w, ch.z, h4.z); h4.w = fmaf(w, ch.w, h4.w);
            float4 uf = *(const float4*)(Ufh + co);
            float4 cc = *(const float4*)(child_c + co);
            f4.x = fmaf(sigmf(wfx.x + uf.x), cc.x, f4.x);
            f4.y = fmaf(sigmf(wfx.y + uf.y), cc.y, f4.y);
            f4.z = fmaf(sigmf(wfx.z + uf.z), cc.z, f4.z);
            f4.w = fmaf(sigmf(wfx.w + uf.w), cc.w, f4.w);
        }
    }
    *(float4*)(hhat + mo) = h4;
    *(float4*)(sfc  + mo) = f4;
}

// ---------------- fused gate epilogue ---------------------------------------
__global__ void finalize_kernel(
    const float* __restrict__ WiX, const float* __restrict__ UiH,
    const float* __restrict__ WcX, const float* __restrict__ UcH,
    const float* __restrict__ WoX, const float* __restrict__ UoH,
    const float* __restrict__ sfc,
    float* __restrict__ outh, float* __restrict__ outc, int n4)
{
    int i = blockIdx.x * blockDim.x + threadIdx.x;
    if (i >= n4) return;
    float4 wi = ((const float4*)WiX)[i], ui = ((const float4*)UiH)[i];
    float4 wc = ((const float4*)WcX)[i], uc = ((const float4*)UcH)[i];
    float4 wo = ((const float4*)WoX)[i], uo = ((const float4*)UoH)[i];
    float4 sf = ((const float4*)sfc)[i];
    float4 h4, c4;
#define DO_COMP(C)                                                   \
    {                                                                \
        float ig = sigmf(wi.C + ui.C);                               \
        float ct = tanhf_(wc.C + uc.C);                              \
        float c  = fmaf(ig, ct, sf.C);                               \
        float o  = sigmf(wo.C + uo.C);                               \
        c4.C = c;                                                    \
        h4.C = o * tanhf_(c);                                        \
    }
    DO_COMP(x) DO_COMP(y) DO_COMP(z) DO_COMP(w)
#undef DO_COMP
    ((float4*)outh)[i] = h4;
    ((float4*)outc)[i] = c4;
}

// ---------------- launch ----------------------------------------------------
extern "C" void kernel_launch(void* const* d_in, const int* in_sizes, int n_in,
                              void* d_out, int out_size)
{
    const float* x_emb   = (const float*)d_in[0];
    const float* child_h = (const float*)d_in[1];
    const float* child_c = (const float*)d_in[2];
    const int*   ci      = (const int*)d_in[3];
    const int*   chi     = (const int*)d_in[4];
    const float* Wi_w = (const float*)d_in[5];
    const float* Ui_w = (const float*)d_in[6];
    const float* Wf_w = (const float*)d_in[7];
    const float* Uf_w = (const float*)d_in[8];
    const float* Wo_w = (const float*)d_in[9];
    const float* Uo_w = (const float*)d_in[10];
    const float* Wc_w = (const float*)d_in[11];
    const float* Uc_w = (const float*)d_in[12];
    const float* Wa_w = (const float*)d_in[13];
    const float* Ua_w = (const float*)d_in[14];
    const float* Wi_b = (const float*)d_in[15];
    const float* Wf_b = (const float*)d_in[16];
    const float* Wo_b = (const float*)d_in[17];
    const float* Wc_b = (const float*)d_in[18];
    const float* Wa_b = (const float*)d_in[19];
    const float* v_w  = (const float*)d_in[20];

    const int M = in_sizes[0] / HDIM;
    const int L = in_sizes[3];

    float* arena = nullptr;
    cudaGetSymbolAddress((void**)&arena, g_arena);
    float* WiX  = arena + 0 * MHS;
    float* WfX  = arena + 1 * MHS;
    float* WoX  = arena + 2 * MHS;
    float* WcX  = arena + 3 * MHS;
    float* Bx   = arena + 4 * MHS;
    float* Ah   = arena + 5 * MHS;
    float* Ufh  = arena + 6 * MHS;
    float* UiH  = arena + 7 * MHS;
    float* UcH  = arena + 8 * MHS;
    float* UoH  = arena + 9 * MHS;
    float* hhat = arena + 10 * MHS;
    float* sfc  = arena + 11 * MHS;

    // CSR build
    zero_int_kernel<<<(M + 255) / 256, 256>>>(M);
    hist_kernel<<<(L + 255) / 256, 256>>>(ci, L);
    scan_kernel<<<1, 1024>>>(M);
    scatter_kernel<<<(L + 255) / 256, 256>>>(ci, chi, L);

    // GEMM batch 1: x_emb x {Wi,Wf,Wo,Wc,Ua}, child_h x {Wa,Uf}
    GemmBatch b1 = {};
    b1.A[0] = x_emb;   b1.B[0] = Wi_w; b1.bias[0] = Wi_b; b1.C[0] = WiX;
    b1.A[1] = x_emb;   b1.B[1] = Wf_w; b1.bias[1] = Wf_b; b1.C[1] = WfX;
    b1.A[2] = x_emb;   b1.B[2] = Wo_w; b1.bias[2] = Wo_b; b1.C[2] = WoX;
    b1.A[3] = x_emb;   b1.B[3] = Wc_w; b1.bias[3] = Wc_b; b1.C[3] = WcX;
    b1.A[4] = x_emb;   b1.B[4] = Ua_w; b1.bias[4] = nullptr; b1.C[4] = Bx;
    b1.A[5] = child_h; b1.B[5] = Wa_w; b1.bias[5] = Wa_b; b1.C[5] = Ah;
    b1.A[6] = child_h; b1.B[6] = Uf_w; b1.bias[6] = nullptr; b1.C[6] = Ufh;
    dim3 g1((M + 127) / 128, 1, 7);
    gemm_nt_kernel<<<g1, 256>>>(b1, M);

    // attention + f-gate segment reduction
    segment_kernel<<<(M + 7) / 8, 256>>>(Bx, Ah, WfX, Ufh, child_h, child_c,
                                         v_w, hhat, sfc, M);

    // GEMM batch 2: hhat x {Ui,Uc,Uo}
    GemmBatch b2 = {};
    b2.A[0] = hhat; b2.B[0] = Ui_w; b2.bias[0] = nullptr; b2.C[0] = UiH;
    b2.A[1] = hhat; b2.B[1] = Uc_w; b2.bias[1] = nullptr; b2.C[1] = UcH;
    b2.A[2] = hhat; b2.B[2] = Uo_w; b2.bias[2] = nullptr; b2.C[2] = UoH;
    dim3 g2((M + 127) / 128, 1, 3);
    gemm_nt_kernel<<<g2, 256>>>(b2, M);

    float* outh = (float*)d_out;
    float* outc = outh + (long long)M * HDIM;
    finalize_kernel<<<(M * 32 + 255) / 256, 256>>>(WiX, UiH, WcX, UcH, WoX, UoH,
                                                   sfc, outh, outc, M * 32);
}